// round 1
// baseline (speedup 1.0000x reference)
#include <cuda_runtime.h>
#include <math.h>

// ---------------------------------------------------------------------------
// Fused GatedEquivariant x2 + scalar head + masked segment-sum, fp32.
//
// Inputs (metadata order):
//  0 s   (1,N,128) f32      1 v   (1,N,3,128) f32    2 r (unused)
//  3 batch_mask (128,N,1)   4 w1 (2,128,128)         5 w2 (2,128,128)
//  6 a1w (2,256,128)        7 a1b (2,128)            8 a2w (2,128,256)
//  9 a2b (2,256)           10 out_w (128,1)         11 out_b (1,)
// Output: (128,1) f32
// ---------------------------------------------------------------------------

#define F        128
#define TM       64          // atoms per CTA
#define NTHREADS 256
#define KC       16          // K-rows per staged weight chunk
#define NGRAPHS  128

// SMEM layout (floats):
//  sS [TM][F]          8192
//  sV [3][TM][F]      24576
//  sN [TM][F]          8192   (n2, later gate)
//  sH [TM][F]          8192   (h1)
//  sW [2][KC*F]        4096   (weight staging, double buffered)
//  sc [TM]               64
#define SMEM_FLOATS (TM*F + 3*TM*F + TM*F + TM*F + 2*KC*F + TM)
#define SMEM_BYTES  (SMEM_FLOATS * 4)

// Register-tiled GEMM: out[TM][128-col-slice] += act[TM][K] @ W[K][128],
// weights streamed gmem(L2) -> smem double-buffered. Each thread owns an
// 8-atom x 4-col accumulator tile. Thread map: tg = tid&31 (g0 = tg*4),
// ta = tid>>5 (a0 = ta*8): weight LDS = coalesced full 512B rows,
// activation LDS = warp-uniform broadcast.
__device__ __forceinline__ void gemm_tile(
    const float* __restrict__ act,   // smem activations, row stride F
    const float* __restrict__ wg,    // gmem weight base (row 0), element (f,c) = wg[f*ldw + c]
    int ldw,
    float* __restrict__ sW,          // staging (2 buffers of KC*F)
    float (&acc)[8][4], int a0, int g0, int K)
{
    const int t  = threadIdx.x;
    const int r0 = t >> 5,          c0 = (t & 31) << 2;          // f4 slot t
    const int r1 = (t + 256) >> 5,  c1 = c0;                      // f4 slot t+256

    __syncthreads();   // protect sW from previous use; publish caller's smem writes
    {
        float4 q0 = *reinterpret_cast<const float4*>(wg + (size_t)r0 * ldw + c0);
        float4 q1 = *reinterpret_cast<const float4*>(wg + (size_t)r1 * ldw + c1);
        *reinterpret_cast<float4*>(sW + r0 * F + c0) = q0;
        *reinterpret_cast<float4*>(sW + r1 * F + c1) = q1;
    }
    __syncthreads();

    const int nchunk = K / KC;
    for (int ch = 0; ch < nchunk; ++ch) {
        float4 n0, n1;
        const bool more = (ch + 1 < nchunk);
        if (more) {   // prefetch next chunk into registers (hidden under compute)
            const float* wn = wg + (size_t)(ch + 1) * KC * ldw;
            n0 = *reinterpret_cast<const float4*>(wn + (size_t)r0 * ldw + c0);
            n1 = *reinterpret_cast<const float4*>(wn + (size_t)r1 * ldw + c1);
        }
        const float* cur = sW + (ch & 1) * (KC * F);
        const int fbase = ch * KC;
        #pragma unroll
        for (int f = 0; f < KC; f += 4) {
            float4 wv0 = *reinterpret_cast<const float4*>(cur + (f + 0) * F + g0);
            float4 wv1 = *reinterpret_cast<const float4*>(cur + (f + 1) * F + g0);
            float4 wv2 = *reinterpret_cast<const float4*>(cur + (f + 2) * F + g0);
            float4 wv3 = *reinterpret_cast<const float4*>(cur + (f + 3) * F + g0);
            #pragma unroll
            for (int a = 0; a < 8; ++a) {
                float4 av = *reinterpret_cast<const float4*>(
                    act + (size_t)(a0 + a) * F + fbase + f);
                acc[a][0] += av.x * wv0.x + av.y * wv1.x + av.z * wv2.x + av.w * wv3.x;
                acc[a][1] += av.x * wv0.y + av.y * wv1.y + av.z * wv2.y + av.w * wv3.y;
                acc[a][2] += av.x * wv0.z + av.y * wv1.z + av.z * wv2.z + av.w * wv3.z;
                acc[a][3] += av.x * wv0.w + av.y * wv1.w + av.z * wv2.w + av.w * wv3.w;
            }
        }
        if (more) {
            float* nb = sW + ((ch + 1) & 1) * (KC * F);
            *reinterpret_cast<float4*>(nb + r0 * F + c0) = n0;
            *reinterpret_cast<float4*>(nb + r1 * F + c1) = n1;
        }
        __syncthreads();
    }
}

__global__ __launch_bounds__(NTHREADS, 1)
void fused_equivariant_kernel(
    const float* __restrict__ s_in, const float* __restrict__ v_in,
    const float* __restrict__ mask,
    const float* __restrict__ w1, const float* __restrict__ w2,
    const float* __restrict__ a1w, const float* __restrict__ a1b,
    const float* __restrict__ a2w, const float* __restrict__ a2b,
    const float* __restrict__ out_w, const float* __restrict__ out_b,
    float* __restrict__ out, int natoms)
{
    extern __shared__ float sm[];
    float* sS   = sm;
    float* sV   = sS + TM * F;
    float* sN   = sV + 3 * TM * F;
    float* sH   = sN + TM * F;
    float* sW   = sH + TM * F;
    float* sc_s = sW + 2 * KC * F;

    const int t  = threadIdx.x;
    const int A0 = blockIdx.x * TM;
    const int g0 = (t & 31) << 2;   // 4 output cols
    const int a0 = (t >> 5) << 3;   // 8 atoms

    // ---- Load s tile (zero-pad past natoms) ----
    for (int j = t; j < TM * F / 4; j += NTHREADS) {
        int atom = j >> 5;
        float4 val = make_float4(0.f, 0.f, 0.f, 0.f);
        if (A0 + atom < natoms)
            val = *reinterpret_cast<const float4*>(
                s_in + (size_t)(A0 + atom) * F + ((j & 31) << 2));
        *reinterpret_cast<float4*>(sS + j * 4) = val;
    }
    // ---- Load v tile, transposing to [c][atom][f] ----
    for (int j = t; j < 3 * TM * F / 4; j += NTHREADS) {
        int off  = j * 4;
        int atom = off / 384;
        int rem  = off - atom * 384;
        int c    = rem >> 7;
        int f    = rem & 127;
        float4 val = make_float4(0.f, 0.f, 0.f, 0.f);
        if (A0 + atom < natoms)
            val = *reinterpret_cast<const float4*>(
                v_in + (size_t)(A0 + atom) * 384 + rem);
        *reinterpret_cast<float4*>(sV + (size_t)c * TM * F + atom * F + f) = val;
    }
    // (visibility handled by gemm_tile's entry __syncthreads)

    for (int layer = 0; layer < 2; ++layer) {
        const float* W1  = w1  + (size_t)layer * F * F;
        const float* W2  = w2  + (size_t)layer * F * F;
        const float* A1W = a1w + (size_t)layer * 2 * F * F;
        const float* A1B = a1b + (size_t)layer * F;
        const float* A2W = a2w + (size_t)layer * F * 2 * F;
        const float* A2B = a2b + (size_t)layer * 2 * F;

        // ---- v2 = v @ w2 per spatial c; n2 = sqrt(sum_c v2^2) ----
        float acc2[8][4];
        #pragma unroll
        for (int a = 0; a < 8; ++a)
            #pragma unroll
            for (int g = 0; g < 4; ++g) acc2[a][g] = 0.f;
        for (int c = 0; c < 3; ++c) {
            float acc[8][4] = {};
            gemm_tile(sV + (size_t)c * TM * F, W2, F, sW, acc, a0, g0, F);
            #pragma unroll
            for (int a = 0; a < 8; ++a)
                #pragma unroll
                for (int g = 0; g < 4; ++g) acc2[a][g] += acc[a][g] * acc[a][g];
        }
        #pragma unroll
        for (int a = 0; a < 8; ++a) {
            float4 o = make_float4(sqrtf(acc2[a][0]), sqrtf(acc2[a][1]),
                                   sqrtf(acc2[a][2]), sqrtf(acc2[a][3]));
            *reinterpret_cast<float4*>(sN + (size_t)(a0 + a) * F + g0) = o;
        }

        // ---- h1 = silu([s, n2] @ a1w + a1b) ----
        {
            float acc[8][4] = {};
            gemm_tile(sS, A1W, F, sW, acc, a0, g0, F);                    // rows 0..127  (s)
            gemm_tile(sN, A1W + (size_t)F * F, F, sW, acc, a0, g0, F);    // rows 128..255 (n2)
            float4 b = *reinterpret_cast<const float4*>(A1B + g0);
            const float* bp = reinterpret_cast<const float*>(&b);
            #pragma unroll
            for (int a = 0; a < 8; ++a) {
                float4 o;
                float* op = reinterpret_cast<float*>(&o);
                #pragma unroll
                for (int g = 0; g < 4; ++g) {
                    float x = acc[a][g] + bp[g];
                    op[g] = x / (1.f + expf(-x));
                }
                *reinterpret_cast<float4*>(sH + (size_t)(a0 + a) * F + g0) = o;
            }
        }

        // ---- h2 = h1 @ a2w + a2b ; split into s_new (cols 0..127) and gate ----
        {
            float accs[8][4] = {};
            gemm_tile(sH, A2W, 2 * F, sW, accs, a0, g0, F);        // first half
            float accg[8][4] = {};
            gemm_tile(sH, A2W + F, 2 * F, sW, accg, a0, g0, F);    // second half (gate)
            float4 b1 = *reinterpret_cast<const float4*>(A2B + g0);
            float4 b2 = *reinterpret_cast<const float4*>(A2B + F + g0);
            const float* b1p = reinterpret_cast<const float*>(&b1);
            const float* b2p = reinterpret_cast<const float*>(&b2);
            #pragma unroll
            for (int a = 0; a < 8; ++a) {
                float4 os, og;
                float* osp = reinterpret_cast<float*>(&os);
                float* ogp = reinterpret_cast<float*>(&og);
                #pragma unroll
                for (int g = 0; g < 4; ++g) {
                    osp[g] = accs[a][g] + b1p[g];
                    ogp[g] = accg[a][g] + b2p[g];
                }
                *reinterpret_cast<float4*>(sS + (size_t)(a0 + a) * F + g0) = os;  // s_new
                *reinterpret_cast<float4*>(sN + (size_t)(a0 + a) * F + g0) = og;  // gate
            }
        }

        // ---- v_new[c] = gate * (v[c] @ w1), written back in place ----
        for (int c = 0; c < 3; ++c) {
            float acc[8][4] = {};
            gemm_tile(sV + (size_t)c * TM * F, W1, F, sW, acc, a0, g0, F);
            // gemm_tile ends with __syncthreads: all reads of sV[c] complete
            #pragma unroll
            for (int a = 0; a < 8; ++a) {
                float4 gt = *reinterpret_cast<const float4*>(
                    sN + (size_t)(a0 + a) * F + g0);
                float4 o = make_float4(gt.x * acc[a][0], gt.y * acc[a][1],
                                       gt.z * acc[a][2], gt.w * acc[a][3]);
                *reinterpret_cast<float4*>(
                    sV + (size_t)c * TM * F + (size_t)(a0 + a) * F + g0) = o;
            }
        }
        __syncthreads();
    }

    // ---- sc[atom] = s @ out_w + out_b (4 threads per atom) ----
    {
        int atom = t >> 2;
        int seg  = t & 3;
        float sum = 0.f;
        const float* row = sS + (size_t)atom * F + seg * 32;
        const float* wrow = out_w + seg * 32;
        #pragma unroll
        for (int g = 0; g < 32; g += 4) {
            float4 sv = *reinterpret_cast<const float4*>(row + g);
            float4 wv = *reinterpret_cast<const float4*>(wrow + g);
            sum += sv.x * wv.x + sv.y * wv.y + sv.z * wv.z + sv.w * wv.w;
        }
        sum += __shfl_down_sync(0xffffffffu, sum, 2);
        sum += __shfl_down_sync(0xffffffffu, sum, 1);
        if (seg == 0) sc_s[atom] = sum + out_b[0];
    }
    __syncthreads();

    // ---- masked segment-sum: warp per graph, coalesced mask reads ----
    {
        int warp = t >> 5, lane = t & 31;
        for (int b = warp; b < NGRAPHS; b += 8) {
            const float* mrow = mask + (size_t)b * natoms + A0;
            float p = 0.f;
            if (A0 + lane      < natoms) p += sc_s[lane]      * mrow[lane];
            if (A0 + lane + 32 < natoms) p += sc_s[lane + 32] * mrow[lane + 32];
            #pragma unroll
            for (int o = 16; o; o >>= 1) p += __shfl_down_sync(0xffffffffu, p, o);
            if (lane == 0) atomicAdd(out + b, p);
        }
    }
}

__global__ void zero_out_kernel(float* out, int n)
{
    int i = blockIdx.x * blockDim.x + threadIdx.x;
    if (i < n) out[i] = 0.f;
}

extern "C" void kernel_launch(void* const* d_in, const int* in_sizes, int n_in,
                              void* d_out, int out_size)
{
    const float* s    = (const float*)d_in[0];
    const float* v    = (const float*)d_in[1];
    /* d_in[2] = r, unused */
    const float* mask = (const float*)d_in[3];
    const float* w1   = (const float*)d_in[4];
    const float* w2   = (const float*)d_in[5];
    const float* a1w  = (const float*)d_in[6];
    const float* a1b  = (const float*)d_in[7];
    const float* a2w  = (const float*)d_in[8];
    const float* a2b  = (const float*)d_in[9];
    const float* ow   = (const float*)d_in[10];
    const float* ob   = (const float*)d_in[11];
    float* out = (float*)d_out;

    const int natoms = in_sizes[0] / F;

    cudaFuncSetAttribute(fused_equivariant_kernel,
                         cudaFuncAttributeMaxDynamicSharedMemorySize, SMEM_BYTES);

    zero_out_kernel<<<1, 128>>>(out, out_size);

    int nblocks = (natoms + TM - 1) / TM;
    fused_equivariant_kernel<<<nblocks, NTHREADS, SMEM_BYTES>>>(
        s, v, mask, w1, w2, a1w, a1b, a2w, a2b, ow, ob, out, natoms);
}

// round 2
// speedup vs baseline: 1.0743x; 1.0743x over previous
#include <cuda_runtime.h>
#include <math.h>

// ---------------------------------------------------------------------------
// Fused GatedEquivariant x2 + scalar head + masked segment-sum, fp32.
// Round 2: 512 threads/CTA (16 warps), merged-plane GEMMs sharing one weight
// staging stream, halved barrier count.
//
// Inputs (metadata order):
//  0 s   (1,N,128) f32      1 v   (1,N,3,128) f32    2 r (unused)
//  3 batch_mask (128,N,1)   4 w1 (2,128,128)         5 w2 (2,128,128)
//  6 a1w (2,256,128)        7 a1b (2,128)            8 a2w (2,128,256)
//  9 a2b (2,256)           10 out_w (128,1)         11 out_b (1,)
// Output: (128,1) f32
// ---------------------------------------------------------------------------

#define F        128
#define TM       64          // atoms per CTA
#define NT       512
#define KC       16          // K-rows per staged weight chunk
#define TMF      (TM * F)
#define NGRAPHS  128

// SMEM (floats): sS[TM][F], sV[3][TM][F], sN[TM][F], sH[TM][F],
//                sW[2][KC*256], sc[TM]
#define SMEM_FLOATS (6 * TMF + 2 * KC * 256 + TM)
#define SMEM_BYTES  (SMEM_FLOATS * 4)

// Merged register-tiled GEMM.
//  NPA = activation planes (stride TMF), NPW = weight column blocks of 128.
//  Each thread owns a (NPA x 4 atoms) x (NPW x 4 cols) accumulator tile.
//  acc[p][w][a*4+g] += act[p][a0+a][k] * W[k][w*128 + g0+g], k in [0,K).
//  Weight chunks (KC rows x NPW*128 cols, contiguous) stream gmem(L2) -> smem
//  double-buffered with register prefetch.
//  Thread map: g0=(t&31)*4 -> weight LDS coalesced; a0=(t>>5)*4 -> act LDS
//  warp-uniform broadcast.
template<int NPA, int NPW>
__device__ __forceinline__ void gemm_tile(
    const float* __restrict__ act,   // smem, NPA planes of [TM][F]
    const float* __restrict__ wg,    // gmem weights [K][NPW*128] contiguous
    float* __restrict__ sW,          // staging: 2 buffers of KC*NPW*128
    float (&acc)[NPA][NPW][16], int a0, int g0, int K)
{
    const int t   = threadIdx.x;
    const int LDW = NPW * F;                 // staged row width

    __syncthreads();   // protect sW from prior use; publish caller's smem writes
    #pragma unroll
    for (int i = 0; i < NPW; ++i)
        reinterpret_cast<float4*>(sW)[t + i * NT] =
            reinterpret_cast<const float4*>(wg)[t + i * NT];
    __syncthreads();

    const int nchunk = K / KC;
    for (int ch = 0; ch < nchunk; ++ch) {
        float4 pf[NPW];
        const bool more = (ch + 1 < nchunk);
        if (more) {
            const float4* wn = reinterpret_cast<const float4*>(
                wg + (size_t)(ch + 1) * KC * LDW);
            #pragma unroll
            for (int i = 0; i < NPW; ++i) pf[i] = wn[t + i * NT];
        }
        const float* cur = sW + (ch & 1) * (KC * LDW);
        const int fb = ch * KC;
        #pragma unroll
        for (int f = 0; f < KC; f += 4) {
            float4 wv[4][NPW];
            #pragma unroll
            for (int k = 0; k < 4; ++k)
                #pragma unroll
                for (int w = 0; w < NPW; ++w)
                    wv[k][w] = *reinterpret_cast<const float4*>(
                        cur + (f + k) * LDW + w * F + g0);
            #pragma unroll
            for (int p = 0; p < NPA; ++p)
                #pragma unroll
                for (int a = 0; a < 4; ++a) {
                    float4 av = *reinterpret_cast<const float4*>(
                        act + p * TMF + (size_t)(a0 + a) * F + fb + f);
                    #pragma unroll
                    for (int w = 0; w < NPW; ++w) {
                        float* A = &acc[p][w][a * 4];
                        A[0] += av.x*wv[0][w].x + av.y*wv[1][w].x + av.z*wv[2][w].x + av.w*wv[3][w].x;
                        A[1] += av.x*wv[0][w].y + av.y*wv[1][w].y + av.z*wv[2][w].y + av.w*wv[3][w].y;
                        A[2] += av.x*wv[0][w].z + av.y*wv[1][w].z + av.z*wv[2][w].z + av.w*wv[3][w].z;
                        A[3] += av.x*wv[0][w].w + av.y*wv[1][w].w + av.z*wv[2][w].w + av.w*wv[3][w].w;
                    }
                }
        }
        if (more) {
            float4* nb = reinterpret_cast<float4*>(sW + ((ch + 1) & 1) * (KC * LDW));
            #pragma unroll
            for (int i = 0; i < NPW; ++i) nb[t + i * NT] = pf[i];
        }
        __syncthreads();
    }
}

__global__ __launch_bounds__(NT, 1)
void fused_equivariant_kernel(
    const float* __restrict__ s_in, const float* __restrict__ v_in,
    const float* __restrict__ mask,
    const float* __restrict__ w1, const float* __restrict__ w2,
    const float* __restrict__ a1w, const float* __restrict__ a1b,
    const float* __restrict__ a2w, const float* __restrict__ a2b,
    const float* __restrict__ out_w, const float* __restrict__ out_b,
    float* __restrict__ out, int natoms)
{
    extern __shared__ float sm[];
    float* sS   = sm;
    float* sV   = sS + TMF;
    float* sN   = sV + 3 * TMF;
    float* sH   = sN + TMF;
    float* sW   = sH + TMF;
    float* sc_s = sW + 2 * KC * 256;

    const int t  = threadIdx.x;
    const int A0 = blockIdx.x * TM;
    const int g0 = (t & 31) << 2;   // 4 output cols
    const int a0 = (t >> 5) << 2;   // 4 atoms

    // ---- Load s tile (zero-pad past natoms) ----
    for (int j = t; j < TMF / 4; j += NT) {
        int atom = j >> 5;
        float4 val = make_float4(0.f, 0.f, 0.f, 0.f);
        if (A0 + atom < natoms)
            val = *reinterpret_cast<const float4*>(
                s_in + (size_t)(A0 + atom) * F + ((j & 31) << 2));
        *reinterpret_cast<float4*>(sS + j * 4) = val;
    }
    // ---- Load v tile, transposed to [c][atom][f] ----
    for (int j = t; j < 3 * TMF / 4; j += NT) {
        int off  = j * 4;
        int atom = off / 384;
        int rem  = off - atom * 384;
        int c    = rem >> 7;
        int f    = rem & 127;
        float4 val = make_float4(0.f, 0.f, 0.f, 0.f);
        if (A0 + atom < natoms)
            val = *reinterpret_cast<const float4*>(
                v_in + (size_t)(A0 + atom) * 384 + rem);
        *reinterpret_cast<float4*>(sV + (size_t)c * TMF + atom * F + f) = val;
    }
    // (visibility handled by gemm_tile's entry __syncthreads)

    for (int layer = 0; layer < 2; ++layer) {
        const float* W1  = w1  + (size_t)layer * F * F;
        const float* W2  = w2  + (size_t)layer * F * F;
        const float* A1W = a1w + (size_t)layer * 2 * F * F;
        const float* A1B = a1b + (size_t)layer * F;
        const float* A2W = a2w + (size_t)layer * F * 2 * F;
        const float* A2B = a2b + (size_t)layer * 2 * F;

        // ---- v2 = v @ w2 (3 planes share one weight stream); n2 = ||v2|| ----
        {
            float acc[3][1][16] = {};
            gemm_tile<3, 1>(sV, W2, sW, acc, a0, g0, F);
            #pragma unroll
            for (int a = 0; a < 4; ++a) {
                float4 o;
                float* op = reinterpret_cast<float*>(&o);
                #pragma unroll
                for (int g = 0; g < 4; ++g) {
                    int i = a * 4 + g;
                    float q = acc[0][0][i] * acc[0][0][i]
                            + acc[1][0][i] * acc[1][0][i]
                            + acc[2][0][i] * acc[2][0][i];
                    op[g] = sqrtf(q);
                }
                *reinterpret_cast<float4*>(sN + (size_t)(a0 + a) * F + g0) = o;
            }
        }

        // ---- h1 = silu([s, n2] @ a1w + a1b) ----
        {
            float acc[1][1][16] = {};
            gemm_tile<1, 1>(sS, A1W, sW, acc, a0, g0, F);                 // rows 0..127 (s)
            gemm_tile<1, 1>(sN, A1W + (size_t)F * F, sW, acc, a0, g0, F); // rows 128..255 (n2)
            float4 b = *reinterpret_cast<const float4*>(A1B + g0);
            const float* bp = reinterpret_cast<const float*>(&b);
            #pragma unroll
            for (int a = 0; a < 4; ++a) {
                float4 o;
                float* op = reinterpret_cast<float*>(&o);
                #pragma unroll
                for (int g = 0; g < 4; ++g) {
                    float x = acc[0][0][a * 4 + g] + bp[g];
                    op[g] = x / (1.f + __expf(-x));
                }
                *reinterpret_cast<float4*>(sH + (size_t)(a0 + a) * F + g0) = o;
            }
        }

        // ---- h2 = h1 @ a2w + a2b (both 128-col halves in one staging) ----
        {
            float acc[1][2][16] = {};
            gemm_tile<1, 2>(sH, A2W, sW, acc, a0, g0, F);
            float4 b1 = *reinterpret_cast<const float4*>(A2B + g0);
            float4 b2 = *reinterpret_cast<const float4*>(A2B + F + g0);
            const float* b1p = reinterpret_cast<const float*>(&b1);
            const float* b2p = reinterpret_cast<const float*>(&b2);
            #pragma unroll
            for (int a = 0; a < 4; ++a) {
                float4 os, og;
                float* osp = reinterpret_cast<float*>(&os);
                float* ogp = reinterpret_cast<float*>(&og);
                #pragma unroll
                for (int g = 0; g < 4; ++g) {
                    osp[g] = acc[0][0][a * 4 + g] + b1p[g];
                    ogp[g] = acc[0][1][a * 4 + g] + b2p[g];
                }
                *reinterpret_cast<float4*>(sS + (size_t)(a0 + a) * F + g0) = os; // s_new
                *reinterpret_cast<float4*>(sN + (size_t)(a0 + a) * F + g0) = og; // gate
            }
        }

        // ---- v_new = gate * (v @ w1) (3 planes, one weight stream) ----
        {
            float acc[3][1][16] = {};
            gemm_tile<3, 1>(sV, W1, sW, acc, a0, g0, F);
            // gemm_tile's final __syncthreads: all sV reads are complete
            #pragma unroll
            for (int a = 0; a < 4; ++a) {
                float4 gt = *reinterpret_cast<const float4*>(
                    sN + (size_t)(a0 + a) * F + g0);
                const float* gp = reinterpret_cast<const float*>(&gt);
                #pragma unroll
                for (int p = 0; p < 3; ++p) {
                    float4 o;
                    float* op = reinterpret_cast<float*>(&o);
                    #pragma unroll
                    for (int g = 0; g < 4; ++g)
                        op[g] = gp[g] * acc[p][0][a * 4 + g];
                    *reinterpret_cast<float4*>(
                        sV + (size_t)p * TMF + (size_t)(a0 + a) * F + g0) = o;
                }
            }
        }
    }
    __syncthreads();

    // ---- sc[atom] = s @ out_w + out_b (8 threads per atom) ----
    {
        int atom = t >> 3;
        int seg  = t & 7;
        float sum = 0.f;
        const float* row  = sS + (size_t)atom * F + seg * 16;
        const float* wrow = out_w + seg * 16;
        #pragma unroll
        for (int g = 0; g < 16; g += 4) {
            float4 sv = *reinterpret_cast<const float4*>(row + g);
            float4 wv = *reinterpret_cast<const float4*>(wrow + g);
            sum += sv.x * wv.x + sv.y * wv.y + sv.z * wv.z + sv.w * wv.w;
        }
        sum += __shfl_down_sync(0xffffffffu, sum, 4);
        sum += __shfl_down_sync(0xffffffffu, sum, 2);
        sum += __shfl_down_sync(0xffffffffu, sum, 1);
        if (seg == 0) sc_s[atom] = sum + out_b[0];
    }
    __syncthreads();

    // ---- masked segment-sum: warp per graph, coalesced mask reads ----
    {
        int warp = t >> 5, lane = t & 31;
        for (int b = warp; b < NGRAPHS; b += NT / 32) {
            const float* mrow = mask + (size_t)b * natoms + A0;
            float p = 0.f;
            if (A0 + lane      < natoms) p += sc_s[lane]      * mrow[lane];
            if (A0 + lane + 32 < natoms) p += sc_s[lane + 32] * mrow[lane + 32];
            #pragma unroll
            for (int o = 16; o; o >>= 1) p += __shfl_down_sync(0xffffffffu, p, o);
            if (lane == 0) atomicAdd(out + b, p);
        }
    }
}

__global__ void zero_out_kernel(float* out, int n)
{
    int i = blockIdx.x * blockDim.x + threadIdx.x;
    if (i < n) out[i] = 0.f;
}

extern "C" void kernel_launch(void* const* d_in, const int* in_sizes, int n_in,
                              void* d_out, int out_size)
{
    const float* s    = (const float*)d_in[0];
    const float* v    = (const float*)d_in[1];
    /* d_in[2] = r, unused */
    const float* mask = (const float*)d_in[3];
    const float* w1   = (const float*)d_in[4];
    const float* w2   = (const float*)d_in[5];
    const float* a1w  = (const float*)d_in[6];
    const float* a1b  = (const float*)d_in[7];
    const float* a2w  = (const float*)d_in[8];
    const float* a2b  = (const float*)d_in[9];
    const float* ow   = (const float*)d_in[10];
    const float* ob   = (const float*)d_in[11];
    float* out = (float*)d_out;

    const int natoms = in_sizes[0] / F;

    cudaFuncSetAttribute(fused_equivariant_kernel,
                         cudaFuncAttributeMaxDynamicSharedMemorySize, SMEM_BYTES);

    zero_out_kernel<<<1, 128>>>(out, out_size);

    int nblocks = (natoms + TM - 1) / TM;
    fused_equivariant_kernel<<<nblocks, NT, SMEM_BYTES>>>(
        s, v, mask, w1, w2, a1w, a1b, a2w, a2b, ow, ob, out, natoms);
}